// round 1
// baseline (speedup 1.0000x reference)
#include <cuda_runtime.h>
#include <cstdint>

#define B_TOT 512
#define T_LEN 1024
#define F_DIM 128
#define U_DIM 50
#define Z_DIM 200   // 4*U
#define NB    4     // batch rows per CTA

// ---------------- packed f32x2 FMA (Blackwell) ----------------
union F2U { float2 f; unsigned long long u; };

__device__ __forceinline__ float2 fma2(float2 a, float2 b, float2 c) {
    F2U ua, ub, uc, r;
    ua.f = a; ub.f = b; uc.f = c;
    asm("fma.rn.f32x2 %0, %1, %2, %3;" : "=l"(r.u) : "l"(ua.u), "l"(ub.u), "l"(uc.u));
    return r.f;
}

// ---------------- cp.async helpers ----------------
__device__ __forceinline__ void cp16(void* smem_dst, const void* gsrc) {
    unsigned sa = (unsigned)__cvta_generic_to_shared(smem_dst);
    asm volatile("cp.async.ca.shared.global [%0], [%1], 16;\n" :: "r"(sa), "l"(gsrc));
}
__device__ __forceinline__ void cp_commit() {
    asm volatile("cp.async.commit_group;\n");
}
__device__ __forceinline__ void cp_wait_all() {
    asm volatile("cp.async.wait_group 0;\n");
}

// ---------------- activations ----------------
__device__ __forceinline__ float sigm(float x) {
    return 1.f / (1.f + __expf(-x));
}
__device__ __forceinline__ float tanh_fast(float x) {
    float ax = fabsf(x);
    float e  = __expf(-2.f * ax);
    float r  = (1.f - e) / (1.f + e);
    return copysignf(r, x);
}

__global__ void __launch_bounds__(256, 1) lstm_fused_kernel(
    const float* __restrict__ inputs,      // [B, T, F]
    const float* __restrict__ kernel,      // [F, 4U]
    const float* __restrict__ rec_kernel,  // [U, 4U]
    const float* __restrict__ bias,        // [4U]
    const float* __restrict__ dense_w,     // [U]
    const float* __restrict__ dense_b,     // [1]
    float* __restrict__ out)               // [B]
{
    __shared__ float xs[2][NB][F_DIM];   // double-buffered x_t, 16B-aligned rows
    __shared__ float hs[NB][52];         // h (padded 50->52 for float4 reads)
    __shared__ float zs[NB][Z_DIM];      // pre-activation gates

    const int tid = threadIdx.x;
    const int b0  = blockIdx.x * NB;
    const int j   = tid;                 // owned output column (valid if < 200)

    // ---- load weights for column j into registers (packed over reduction dim)
    float2 wk2[64];   // kernel[:, j], pairs over f
    float2 wr2[26];   // rec_kernel[:, j], pairs over u (last pair zero-padded)
    float  bj = 0.f;
    if (j < Z_DIM) {
        #pragma unroll
        for (int q = 0; q < 64; q++)
            wk2[q] = make_float2(kernel[(2*q)     * Z_DIM + j],
                                 kernel[(2*q + 1) * Z_DIM + j]);
        #pragma unroll
        for (int q = 0; q < 25; q++)
            wr2[q] = make_float2(rec_kernel[(2*q)     * Z_DIM + j],
                                 rec_kernel[(2*q + 1) * Z_DIM + j]);
        wr2[25] = make_float2(0.f, 0.f);
        bj = bias[j];
    }

    // ---- init h (incl. pad) to zero
    if (tid < NB * 52) ((float*)hs)[tid] = 0.f;

    // gate-phase mapping (threads 0..199): unit gu of batch gb, c kept in reg
    float c_reg = 0.f;
    const int gu = tid % U_DIM;
    const int gb = tid / U_DIM;

    // ---- preload x_0 into buffer 0
    if (tid < 128) {
        int b = tid >> 5, f4 = tid & 31;
        cp16(&xs[0][b][f4 * 4],
             inputs + ((size_t)(b0 + b) * T_LEN + 0) * F_DIM + f4 * 4);
        cp_commit();
        cp_wait_all();
    }
    __syncthreads();

    for (int t = 0; t < T_LEN; ++t) {
        const int cur = t & 1, nxt = cur ^ 1;

        // prefetch x_{t+1} into the other buffer (consumed-last-iter buffer)
        if (t + 1 < T_LEN && tid < 128) {
            int b = tid >> 5, f4 = tid & 31;
            cp16(&xs[nxt][b][f4 * 4],
                 inputs + ((size_t)(b0 + b) * T_LEN + (t + 1)) * F_DIM + f4 * 4);
            cp_commit();
        }

        if (j < Z_DIM) {
            float2 a0 = make_float2(bj, 0.f);
            float2 a1 = a0, a2 = a0, a3 = a0;

            const float4* x0 = (const float4*)xs[cur][0];
            const float4* x1 = (const float4*)xs[cur][1];
            const float4* x2 = (const float4*)xs[cur][2];
            const float4* x3 = (const float4*)xs[cur][3];
            #pragma unroll
            for (int q = 0; q < 32; q++) {
                float4 v0 = x0[q], v1 = x1[q], v2 = x2[q], v3 = x3[q];
                float2 w0 = wk2[2*q], w1 = wk2[2*q + 1];
                a0 = fma2(w0, make_float2(v0.x, v0.y), a0);
                a1 = fma2(w0, make_float2(v1.x, v1.y), a1);
                a2 = fma2(w0, make_float2(v2.x, v2.y), a2);
                a3 = fma2(w0, make_float2(v3.x, v3.y), a3);
                a0 = fma2(w1, make_float2(v0.z, v0.w), a0);
                a1 = fma2(w1, make_float2(v1.z, v1.w), a1);
                a2 = fma2(w1, make_float2(v2.z, v2.w), a2);
                a3 = fma2(w1, make_float2(v3.z, v3.w), a3);
            }

            const float4* h0 = (const float4*)hs[0];
            const float4* h1 = (const float4*)hs[1];
            const float4* h2 = (const float4*)hs[2];
            const float4* h3 = (const float4*)hs[3];
            #pragma unroll
            for (int q = 0; q < 13; q++) {
                float4 v0 = h0[q], v1 = h1[q], v2 = h2[q], v3 = h3[q];
                float2 w0 = wr2[2*q], w1 = wr2[2*q + 1];
                a0 = fma2(w0, make_float2(v0.x, v0.y), a0);
                a1 = fma2(w0, make_float2(v1.x, v1.y), a1);
                a2 = fma2(w0, make_float2(v2.x, v2.y), a2);
                a3 = fma2(w0, make_float2(v3.x, v3.y), a3);
                a0 = fma2(w1, make_float2(v0.z, v0.w), a0);
                a1 = fma2(w1, make_float2(v1.z, v1.w), a1);
                a2 = fma2(w1, make_float2(v2.z, v2.w), a2);
                a3 = fma2(w1, make_float2(v3.z, v3.w), a3);
            }

            zs[0][j] = a0.x + a0.y;
            zs[1][j] = a1.x + a1.y;
            zs[2][j] = a2.x + a2.y;
            zs[3][j] = a3.x + a3.y;
        }
        __syncthreads();

        // ---- gate phase: c update in registers, h -> smem
        if (tid < NB * U_DIM) {
            float zi = zs[gb][gu];
            float zf = zs[gb][U_DIM     + gu];
            float zg = zs[gb][2 * U_DIM + gu];
            float zo = zs[gb][3 * U_DIM + gu];
            float ig = sigm(zi);
            float fg = sigm(zf);
            float og = sigm(zo);
            float g  = tanh_fast(zg);
            c_reg = fg * c_reg + ig * g;
            hs[gb][gu] = og * tanh_fast(c_reg);
        }
        cp_wait_all();      // x_{t+1} landed (only issuing threads pend; no-op for others)
        __syncthreads();
    }

    // ---- final dense: out[b] = h_last[b] . dense_w + dense_b
    if (tid < NB) {
        float acc = dense_b[0];
        #pragma unroll
        for (int u = 0; u < U_DIM; u++)
            acc += hs[tid][u] * dense_w[u];
        out[b0 + tid] = acc;
    }
}

extern "C" void kernel_launch(void* const* d_in, const int* in_sizes, int n_in,
                              void* d_out, int out_size) {
    const float* inputs     = (const float*)d_in[0];
    const float* kernel     = (const float*)d_in[1];
    const float* rec_kernel = (const float*)d_in[2];
    const float* bias       = (const float*)d_in[3];
    const float* dense_w    = (const float*)d_in[4];
    const float* dense_b    = (const float*)d_in[5];
    float* out = (float*)d_out;

    lstm_fused_kernel<<<B_TOT / NB, 256>>>(inputs, kernel, rec_kernel, bias,
                                           dense_w, dense_b, out);
}